// round 12
// baseline (speedup 1.0000x reference)
#include <cuda_runtime.h>
#include <cuda_bf16.h>
#include <cstdint>
#include <math.h>

typedef unsigned int       u32;
typedef unsigned long long u64;

#define S_MAX 20000
#define S_PAD 20096
#define D_FIX 256

// pool kernel: 128 nodes per CTA in 4 chunks of 32, double-buffered cp.async
#define PB 32
#define PNC 4
#define PNODES (PB * PNC)
#define POOL2_SMEM (2 * PB * 256 * 4 + 2 * PB * 4 + (PNODES + 1) * 4)

// Scratch (device globals: allocation-free per harness rules)
__device__ float g_pooled[S_MAX * D_FIX];       // raw Σ e_i x_i  [S,256]
__device__ float g_denom[S_MAX];                // raw Σ e_i      [S]
__device__ __nv_bfloat16 g_A2[S_PAD * 512];     // pooled bf16: [s][0:256)=hi, [256:512)=lo
__device__ __nv_bfloat16 g_Bhi[256 * 256];      // Wm^T hi  [n][k]
__device__ __nv_bfloat16 g_Blo[256 * 256];      // Wm^T lo  [n][k]

extern __shared__ char dyn_smem[];

__device__ __forceinline__ u32 smem_u32(const void* p) {
    u32 a;
    asm("{ .reg .u64 t; cvta.to.shared.u64 t, %1; cvt.u32.u64 %0, t; }" : "=r"(a) : "l"(p));
    return a;
}
__device__ __forceinline__ u32 pack_bf2(__nv_bfloat16 a, __nv_bfloat16 b) {
    return (u32)__bfloat16_as_ushort(a) | ((u32)__bfloat16_as_ushort(b) << 16);
}
__device__ __forceinline__ void cpasync16(u32 dst, const void* src) {
    asm volatile("cp.async.cg.shared.global [%0], [%1], 16;"
                 :: "r"(dst), "l"(src) : "memory");
}
__device__ __forceinline__ void ldsm4(u32* r, u32 addr) {
    asm volatile("ldmatrix.sync.aligned.m8n8.x4.shared.b16 {%0,%1,%2,%3}, [%4];"
                 : "=r"(r[0]), "=r"(r[1]), "=r"(r[2]), "=r"(r[3]) : "r"(addr));
}
__device__ __forceinline__ void mma_bf16(float* c, const u32* a, const u32* b) {
    asm volatile(
        "mma.sync.aligned.m16n8k16.row.col.f32.bf16.bf16.f32 "
        "{%0,%1,%2,%3}, {%4,%5,%6,%7}, {%8,%9}, {%0,%1,%2,%3};"
        : "+f"(c[0]), "+f"(c[1]), "+f"(c[2]), "+f"(c[3])
        : "r"(a[0]), "r"(a[1]), "r"(a[2]), "r"(a[3]), "r"(b[0]), "r"(b[1]));
}

// ===========================================================================
// Kernel Z: zero the accumulators
// ===========================================================================
__global__ void __launch_bounds__(256) zero_kernel() {
    const int i = blockIdx.x * 256 + threadIdx.x;
    const float4 z = make_float4(0.f, 0.f, 0.f, 0.f);
    if (i < S_MAX * (D_FIX / 4)) ((float4*)g_pooled)[i] = z;
    if (i < S_MAX / 4)           ((float4*)g_denom)[i]  = z;
}

// ===========================================================================
// Kernel P: split Wm^T into bf16 hi/lo  ([n][k], K-contiguous)
// ===========================================================================
__global__ void __launch_bounds__(256) prep_b_kernel(const float* __restrict__ Wm) {
    const int n = blockIdx.x;
    const int k = threadIdx.x;
    const float v = Wm[k * 256 + n];
    const __nv_bfloat16 hi = __float2bfloat16(v);
    const __nv_bfloat16 lo = __float2bfloat16(v - __bfloat162float(hi));
    g_Bhi[n * 256 + k] = hi;
    g_Blo[n * 256 + k] = lo;
}

// ===========================================================================
// Kernel A: pipelined node pooling. 128 nodes/CTA in 4 chunks of 32;
// cp.async double buffer: stage chunk c+1 while computing chunk c, so each
// CTA keeps DRAM loads in flight continuously. acc/cur carry across chunks;
// sentinel idxs[lenAll] = -1 forces the final flush.
// __syncthreads() after idxs staging (R11 fix: cur=idxs[0] raced the write).
// ===========================================================================
__global__ void __launch_bounds__(256) node_pool_kernel(
    const float* __restrict__ x,
    const float* __restrict__ weights,
    const float* __restrict__ Wg,
    const float* __restrict__ bg,
    const float* __restrict__ p_,
    const int*   __restrict__ index,
    int N)
{
    float* xs0 = (float*)dyn_smem;                 // [2][PB*256]
    float* es  = xs0 + 2 * PB * 256;               // [2][PB]
    int*   idxs = (int*)(es + 2 * PB);             // [PNODES+1]

    const int base = blockIdx.x * PNODES;
    const int lenAll = min(PNODES, N - base);
    const int ncc = (lenAll + PB - 1) / PB;
    const int t = threadIdx.x;
    const int w = t >> 5;
    const int l = t & 31;

    if (t < lenAll) idxs[t] = index[base + t];     // lenAll <= 128 < 256
    if (t == 0)     idxs[lenAll] = -1;
    __syncthreads();                               // idxs visible to ALL warps

    const u32 sxs = smem_u32(xs0);

    auto stage = [&](int c, int b) {
        const int cb = base + c * PB;
        const int lenC = min(PB, N - cb);
        const u32 dstb = sxs + b * (PB * 256 * 4);
        const float4* src = (const float4*)x + (size_t)cb * 64;
        #pragma unroll
        for (int i = 0; i < 8; i++) {
            const int id = t + i * 256;            // 0..2047 float4 slots
            if ((id >> 6) < lenC)
                cpasync16(dstb + id * 16, src + id);
        }
        asm volatile("cp.async.commit_group;" ::: "memory");
    };

    const float4* Wg4 = (const float4*)Wg;
    const float4 wga = Wg4[l];
    const float4 wgb = Wg4[32 + l];
    const float bgv = bg[0];
    const float pv  = p_[0];

    stage(0, 0);

    float acc = 0.f;
    int cur = idxs[0];

    for (int c = 0; c < ncc; c++) {
        const int b = c & 1;
        if (c + 1 < ncc) {
            stage(c + 1, b ^ 1);
            asm volatile("cp.async.wait_group 1;" ::: "memory");
        } else {
            asm volatile("cp.async.wait_group 0;" ::: "memory");
        }
        __syncthreads();

        const int cb   = base + c * PB;
        const int lenC = min(PB, lenAll - c * PB);
        float* xsb = xs0 + b * PB * 256;
        float* esb = es + b * PB;

        // gate dots: 4 nodes per warp, batched shuffle reduces
        float pdv[4], wv[4];
        const float4* xs4 = (const float4*)xsb;
        #pragma unroll
        for (int jj = 0; jj < 4; jj++) {
            const int j = w + jj * 8;
            pdv[jj] = 0.f; wv[jj] = 1.f;
            if (j < lenC) {
                const float4 xa = xs4[j * 64 + l];
                const float4 xb = xs4[j * 64 + 32 + l];
                pdv[jj] = xa.x * wga.x + xa.y * wga.y + xa.z * wga.z + xa.w * wga.w
                        + xb.x * wgb.x + xb.y * wgb.y + xb.z * wgb.z + xb.w * wgb.w;
                wv[jj] = __ldg(&weights[cb + j]);
            }
        }
        #pragma unroll
        for (int jj = 0; jj < 4; jj++) {
            float pd = pdv[jj];
            #pragma unroll
            for (int off = 16; off; off >>= 1)
                pd += __shfl_xor_sync(0xffffffffu, pd, off);
            pdv[jj] = pd;
        }
        #pragma unroll
        for (int jj = 0; jj < 4; jj++) {
            const int j = w + jj * 8;
            if (j < lenC && l == 0)
                esb[j] = expf(fmaf(pv, logf(wv[jj]), pdv[jj] + bgv));
        }
        __syncthreads();

        // denominators: one atomic per node, warp-parallel
        if (t < lenC) atomicAdd(&g_denom[idxs[c * PB + t]], esb[t]);

        // thread-per-dim accumulation; acc/cur carry across chunks
        for (int j = 0; j < lenC; j++) {
            acc = fmaf(esb[j], xsb[j * 256 + t], acc);
            const int nxt = idxs[c * PB + j + 1];
            if (nxt != cur) {
                atomicAdd(&g_pooled[(size_t)cur * 256 + t], acc);
                acc = 0.f;
                cur = nxt;
            }
        }
        __syncthreads();   // buffer b reused at c+2
    }
}

// ===========================================================================
// Kernel C: convert pooled fp32 -> bf16 hi|lo; zero-fill padded rows
// ===========================================================================
__global__ void __launch_bounds__(256) convert_a_kernel(int S) {
    const int idx = blockIdx.x * 256 + threadIdx.x;
    if (idx >= S_PAD * 64) return;
    const int row = idx >> 6;
    const int c4  = idx & 63;
    float4 v = make_float4(0.f, 0.f, 0.f, 0.f);
    if (row < S) v = ((const float4*)g_pooled)[idx];
    const __nv_bfloat16 h0 = __float2bfloat16(v.x);
    const __nv_bfloat16 h1 = __float2bfloat16(v.y);
    const __nv_bfloat16 h2 = __float2bfloat16(v.z);
    const __nv_bfloat16 h3 = __float2bfloat16(v.w);
    const __nv_bfloat16 l0 = __float2bfloat16(v.x - __bfloat162float(h0));
    const __nv_bfloat16 l1 = __float2bfloat16(v.y - __bfloat162float(h1));
    const __nv_bfloat16 l2 = __float2bfloat16(v.z - __bfloat162float(h2));
    const __nv_bfloat16 l3 = __float2bfloat16(v.w - __bfloat162float(h3));
    *(uint2*)&g_A2[(size_t)row * 512 + c4 * 4] =
        make_uint2(pack_bf2(h0, h1), pack_bf2(h2, h3));
    *(uint2*)&g_A2[(size_t)row * 512 + 256 + c4 * 4] =
        make_uint2(pack_bf2(l0, l1), pack_bf2(l2, l3));
}

// ===========================================================================
// Kernel B: bf16 mma.sync GEMM, virtual K = 768 (hi*hi + lo*hi + hi*lo).
// BM=128, BN=128, BK=64; cp.async double-buffered smem; ldmatrix fragments.
// ===========================================================================
#define GBM 128
#define GBN 128
#define GBK 64
#define ASTR 72
#define TBYTES (128 * ASTR * 2)
#define GEMM_SMEM (4 * TBYTES)

__global__ void __launch_bounds__(256, 2) mma_gemm_kernel(
    const float* __restrict__ bmv_,
    float* __restrict__ out,
    int S)
{
    const u32 sbase = smem_u32(dyn_smem);
    const int t = threadIdx.x;
    const int lane = t & 31;
    const int w = t >> 5;
    const int warpM = w & 3;
    const int warpN = w >> 2;
    const int lr = lane >> 2;
    const int lc = lane & 3;
    const int q  = lane >> 3;
    const int mr = lane & 7;

    const int aro = (q & 1) * 8 + mr;
    const int ako = (q >> 1) * 8;
    const int bro = (q >> 1) * 8 + mr;
    const int bko = (q & 1) * 8;

    const int rowBase = blockIdx.x * GBM;
    const int colBase = blockIdx.y * GBN;

    const int sr = t >> 3;
    const int sk8 = (t & 7) * 8;

    float c[2][8][4];
    #pragma unroll
    for (int i = 0; i < 2; i++)
        #pragma unroll
        for (int j = 0; j < 8; j++)
            #pragma unroll
            for (int qq = 0; qq < 4; qq++) c[i][j][qq] = 0.f;

    auto stage = [&](int ch, int buf) {
        const int kc = ch & 3;
        const int acol = kc * 64 + ((ch >= 4 && ch < 8) ? 256 : 0);
        const __nv_bfloat16* Bb = (ch < 8) ? g_Bhi : g_Blo;
        const u32 abase = sbase + buf * TBYTES;
        const u32 bbase = sbase + 2 * TBYTES + buf * TBYTES;
        #pragma unroll
        for (int i = 0; i < 4; i++) {
            const int r = sr + i * 32;
            cpasync16(abase + r * (ASTR * 2) + sk8 * 2,
                      &g_A2[(size_t)(rowBase + r) * 512 + acol + sk8]);
            cpasync16(bbase + r * (ASTR * 2) + sk8 * 2,
                      &Bb[(size_t)(colBase + r) * 256 + kc * 64 + sk8]);
        }
        asm volatile("cp.async.commit_group;" ::: "memory");
    };

    stage(0, 0);

    for (int ch = 0; ch < 12; ch++) {
        const int buf = ch & 1;
        if (ch + 1 < 12) {
            stage(ch + 1, buf ^ 1);
            asm volatile("cp.async.wait_group 1;" ::: "memory");
        } else {
            asm volatile("cp.async.wait_group 0;" ::: "memory");
        }
        __syncthreads();

        const u32 abase = sbase + buf * TBYTES;
        const u32 bbase = sbase + 2 * TBYTES + buf * TBYTES;
        #pragma unroll
        for (int kk = 0; kk < 4; kk++) {
            const int k0 = kk * 16;
            u32 a[2][4], b[4][4];
            #pragma unroll
            for (int i = 0; i < 2; i++)
                ldsm4(a[i], abase + (warpM * 32 + i * 16 + aro) * (ASTR * 2)
                                  + (k0 + ako) * 2);
            #pragma unroll
            for (int jp = 0; jp < 4; jp++)
                ldsm4(b[jp], bbase + (warpN * 64 + jp * 16 + bro) * (ASTR * 2)
                                   + (k0 + bko) * 2);
            #pragma unroll
            for (int i = 0; i < 2; i++)
                #pragma unroll
                for (int jp = 0; jp < 4; jp++) {
                    mma_bf16(c[i][2 * jp],     a[i], &b[jp][0]);
                    mma_bf16(c[i][2 * jp + 1], a[i], &b[jp][2]);
                }
        }
        __syncthreads();
    }

    #pragma unroll
    for (int i = 0; i < 2; i++) {
        const int r0 = rowBase + warpM * 32 + i * 16 + lr;
        const int r1 = r0 + 8;
        float inv0 = 0.f, sg0 = 0.f, inv1 = 0.f, sg1 = 0.f;
        if (r0 < S) {
            const float d = g_denom[r0];
            inv0 = __fdividef(1.f, d + 1e-10f); sg0 = d * inv0;
        }
        if (r1 < S) {
            const float d = g_denom[r1];
            inv1 = __fdividef(1.f, d + 1e-10f); sg1 = d * inv1;
        }
        #pragma unroll
        for (int j = 0; j < 8; j++) {
            const int n = colBase + warpN * 64 + j * 8 + lc * 2;
            const float2 bm2 = *(const float2*)&bmv_[n];
            if (r0 < S) {
                float2 o;
                o.x = fmaf(c[i][j][0], inv0, sg0 * bm2.x);
                o.y = fmaf(c[i][j][1], inv0, sg0 * bm2.y);
                *(float2*)&out[(size_t)r0 * 256 + n] = o;
            }
            if (r1 < S) {
                float2 o;
                o.x = fmaf(c[i][j][2], inv1, sg1 * bm2.x);
                o.y = fmaf(c[i][j][3], inv1, sg1 * bm2.y);
                *(float2*)&out[(size_t)r1 * 256 + n] = o;
            }
        }
    }
}

// ===========================================================================
// inputs (metadata order): x, weights, Wg, bg, Wm, bm, p, index, [num_segments]
// ===========================================================================
extern "C" void kernel_launch(void* const* d_in, const int* in_sizes, int n_in,
                              void* d_out, int out_size) {
    const float* x       = (const float*)d_in[0];
    const float* weights = (const float*)d_in[1];
    const float* Wg      = (const float*)d_in[2];
    const float* bg      = (const float*)d_in[3];
    const float* Wm      = (const float*)d_in[4];
    const float* bm      = (const float*)d_in[5];
    const float* p       = (const float*)d_in[6];
    const int*   index   = (const int*)d_in[7];

    const int N = in_sizes[7];
    const int D = in_sizes[2];            // 256
    int S = out_size / D;                 // 20000
    if (S > S_MAX) S = S_MAX;

    cudaFuncSetAttribute(mma_gemm_kernel,
                         cudaFuncAttributeMaxDynamicSharedMemorySize, GEMM_SMEM);
    cudaFuncSetAttribute(node_pool_kernel,
                         cudaFuncAttributeMaxDynamicSharedMemorySize, POOL2_SMEM);

    prep_b_kernel<<<256, 256>>>(Wm);
    zero_kernel<<<(S_MAX * (D_FIX / 4) + 255) / 256, 256>>>();
    node_pool_kernel<<<(N + PNODES - 1) / PNODES, 256, POOL2_SMEM>>>(
        x, weights, Wg, bg, p, index, N);
    convert_a_kernel<<<(S_PAD * 64 + 255) / 256, 256>>>(S);
    dim3 grid((S + GBM - 1) / GBM, D / GBN);
    mma_gemm_kernel<<<grid, 256, GEMM_SMEM>>>(bm, (float*)d_out, S);
}

// round 13
// speedup vs baseline: 1.3816x; 1.3816x over previous
#include <cuda_runtime.h>
#include <cuda_bf16.h>
#include <cstdint>
#include <math.h>

typedef unsigned int       u32;
typedef unsigned long long u64;

#define S_MAX 20000
#define S_PAD 20096
#define D_FIX 256
#define CHUNK 24             // nodes per CTA: smem 24.8KB -> 8 CTAs/SM (thread-capped)
#define POOL_SMEM (CHUNK * 256 * 4 + CHUNK * 4 + (CHUNK + 1) * 4)

// Scratch (device globals: allocation-free per harness rules)
__device__ float g_pooled[S_MAX * D_FIX];       // raw Σ e_i x_i  [S,256]
__device__ float g_denom[S_MAX];                // raw Σ e_i      [S]
__device__ __nv_bfloat16 g_A2[S_PAD * 512];     // pooled bf16: [s][0:256)=hi, [256:512)=lo
__device__ __nv_bfloat16 g_Bhi[256 * 256];      // Wm^T hi  [n][k]
__device__ __nv_bfloat16 g_Blo[256 * 256];      // Wm^T lo  [n][k]

extern __shared__ char dyn_smem[];

__device__ __forceinline__ u32 smem_u32(const void* p) {
    u32 a;
    asm("{ .reg .u64 t; cvta.to.shared.u64 t, %1; cvt.u32.u64 %0, t; }" : "=r"(a) : "l"(p));
    return a;
}
__device__ __forceinline__ u32 pack_bf2(__nv_bfloat16 a, __nv_bfloat16 b) {
    return (u32)__bfloat16_as_ushort(a) | ((u32)__bfloat16_as_ushort(b) << 16);
}
__device__ __forceinline__ void cpasync16(u32 dst, const void* src) {
    asm volatile("cp.async.cg.shared.global [%0], [%1], 16;"
                 :: "r"(dst), "l"(src) : "memory");
}
__device__ __forceinline__ void ldsm4(u32* r, u32 addr) {
    asm volatile("ldmatrix.sync.aligned.m8n8.x4.shared.b16 {%0,%1,%2,%3}, [%4];"
                 : "=r"(r[0]), "=r"(r[1]), "=r"(r[2]), "=r"(r[3]) : "r"(addr));
}
__device__ __forceinline__ void mma_bf16(float* c, const u32* a, const u32* b) {
    asm volatile(
        "mma.sync.aligned.m16n8k16.row.col.f32.bf16.bf16.f32 "
        "{%0,%1,%2,%3}, {%4,%5,%6,%7}, {%8,%9}, {%0,%1,%2,%3};"
        : "+f"(c[0]), "+f"(c[1]), "+f"(c[2]), "+f"(c[3])
        : "r"(a[0]), "r"(a[1]), "r"(a[2]), "r"(a[3]), "r"(b[0]), "r"(b[1]));
}

// ===========================================================================
// Kernel Z: zero the accumulators
// ===========================================================================
__global__ void __launch_bounds__(256) zero_kernel() {
    const int i = blockIdx.x * 256 + threadIdx.x;
    const float4 z = make_float4(0.f, 0.f, 0.f, 0.f);
    if (i < S_MAX * (D_FIX / 4)) ((float4*)g_pooled)[i] = z;
    if (i < S_MAX / 4)           ((float4*)g_denom)[i]  = z;
}

// ===========================================================================
// Kernel P: split Wm^T into bf16 hi/lo  ([n][k], K-contiguous)
// ===========================================================================
__global__ void __launch_bounds__(256) prep_b_kernel(const float* __restrict__ Wm) {
    const int n = blockIdx.x;
    const int k = threadIdx.x;
    const float v = Wm[k * 256 + n];
    const __nv_bfloat16 hi = __float2bfloat16(v);
    const __nv_bfloat16 lo = __float2bfloat16(v - __bfloat162float(hi));
    g_Bhi[n * 256 + k] = hi;
    g_Blo[n * 256 + k] = lo;
}

// ===========================================================================
// Kernel A: node-parallel fused gate + weighted pooling (R10 structure —
// the pipeline IS the CTA count: 8 phase-staggered CTAs/SM keep DRAM busy).
// ===========================================================================
__global__ void __launch_bounds__(256) node_pool_kernel(
    const float* __restrict__ x,
    const float* __restrict__ weights,
    const float* __restrict__ Wg,
    const float* __restrict__ bg,
    const float* __restrict__ p_,
    const int*   __restrict__ index,
    int N)
{
    float* xs  = (float*)dyn_smem;
    float* es  = xs + CHUNK * 256;
    int*   idxs = (int*)(es + CHUNK);

    const int base = blockIdx.x * CHUNK;
    const int len  = min(CHUNK, N - base);
    const int t = threadIdx.x;
    const int w = t >> 5;
    const int l = t & 31;

    if (t < len) idxs[t] = index[base + t];
    if (t == 0)  idxs[len] = -1;

    {
        const float4* src = (const float4*)x + (size_t)base * 64;
        float4* dst = (float4*)xs;
        const int n4 = len * 64;
        #pragma unroll 6
        for (int i = t; i < n4; i += 256) dst[i] = __ldcs(src + i);
    }
    __syncthreads();

    const float4* Wg4 = (const float4*)Wg;
    const float4 wga = Wg4[l];
    const float4 wgb = Wg4[32 + l];
    const float bgv = bg[0];
    const float pv  = p_[0];

    const int NJJ = CHUNK / 8;          // 3 nodes per warp
    float pdv[NJJ], wv[NJJ];
    const float4* xs4 = (const float4*)xs;
    #pragma unroll
    for (int jj = 0; jj < NJJ; jj++) {
        const int j = w + jj * 8;
        pdv[jj] = 0.f; wv[jj] = 1.f;
        if (j < len) {
            const float4 xa = xs4[j * 64 + l];
            const float4 xb = xs4[j * 64 + 32 + l];
            pdv[jj] = xa.x * wga.x + xa.y * wga.y + xa.z * wga.z + xa.w * wga.w
                    + xb.x * wgb.x + xb.y * wgb.y + xb.z * wgb.z + xb.w * wgb.w;
            wv[jj] = __ldg(&weights[base + j]);
        }
    }
    #pragma unroll
    for (int jj = 0; jj < NJJ; jj++) {
        float pd = pdv[jj];
        #pragma unroll
        for (int off = 16; off; off >>= 1)
            pd += __shfl_xor_sync(0xffffffffu, pd, off);
        pdv[jj] = pd;
    }
    #pragma unroll
    for (int jj = 0; jj < NJJ; jj++) {
        const int j = w + jj * 8;
        if (j < len && l == 0)
            es[j] = expf(fmaf(pv, logf(wv[jj]), pdv[jj] + bgv));
    }
    __syncthreads();

    // denominators: one atomic per node, warp-parallel (t < len <= 24)
    if (t < len) atomicAdd(&g_denom[idxs[t]], es[t]);

    // thread-per-dim weighted accumulation + boundary flush
    {
        float acc = 0.f;
        int cur = idxs[0];
        for (int j = 0; j < len; j++) {
            acc = fmaf(es[j], xs[j * 256 + t], acc);
            const int nxt = idxs[j + 1];
            if (nxt != cur) {
                atomicAdd(&g_pooled[(size_t)cur * 256 + t], acc);
                acc = 0.f;
                cur = nxt;
            }
        }
    }
}

// ===========================================================================
// Kernel C: convert pooled fp32 -> bf16 hi|lo; zero-fill padded rows
// ===========================================================================
__global__ void __launch_bounds__(256) convert_a_kernel(int S) {
    const int idx = blockIdx.x * 256 + threadIdx.x;
    if (idx >= S_PAD * 64) return;
    const int row = idx >> 6;
    const int c4  = idx & 63;
    float4 v = make_float4(0.f, 0.f, 0.f, 0.f);
    if (row < S) v = ((const float4*)g_pooled)[idx];
    const __nv_bfloat16 h0 = __float2bfloat16(v.x);
    const __nv_bfloat16 h1 = __float2bfloat16(v.y);
    const __nv_bfloat16 h2 = __float2bfloat16(v.z);
    const __nv_bfloat16 h3 = __float2bfloat16(v.w);
    const __nv_bfloat16 l0 = __float2bfloat16(v.x - __bfloat162float(h0));
    const __nv_bfloat16 l1 = __float2bfloat16(v.y - __bfloat162float(h1));
    const __nv_bfloat16 l2 = __float2bfloat16(v.z - __bfloat162float(h2));
    const __nv_bfloat16 l3 = __float2bfloat16(v.w - __bfloat162float(h3));
    *(uint2*)&g_A2[(size_t)row * 512 + c4 * 4] =
        make_uint2(pack_bf2(h0, h1), pack_bf2(h2, h3));
    *(uint2*)&g_A2[(size_t)row * 512 + 256 + c4 * 4] =
        make_uint2(pack_bf2(l0, l1), pack_bf2(l2, l3));
}

// ===========================================================================
// Kernel B: bf16 mma.sync GEMM, virtual K = 768 (hi*hi + lo*hi + hi*lo).
// BM=128, BN=128, BK=64; cp.async double-buffered smem; ldmatrix fragments.
// ===========================================================================
#define GBM 128
#define GBN 128
#define GBK 64
#define ASTR 72
#define TBYTES (128 * ASTR * 2)
#define GEMM_SMEM (4 * TBYTES)

__global__ void __launch_bounds__(256, 2) mma_gemm_kernel(
    const float* __restrict__ bmv_,
    float* __restrict__ out,
    int S)
{
    const u32 sbase = smem_u32(dyn_smem);
    const int t = threadIdx.x;
    const int lane = t & 31;
    const int w = t >> 5;
    const int warpM = w & 3;
    const int warpN = w >> 2;
    const int lr = lane >> 2;
    const int lc = lane & 3;
    const int q  = lane >> 3;
    const int mr = lane & 7;

    const int aro = (q & 1) * 8 + mr;
    const int ako = (q >> 1) * 8;
    const int bro = (q >> 1) * 8 + mr;
    const int bko = (q & 1) * 8;

    const int rowBase = blockIdx.x * GBM;
    const int colBase = blockIdx.y * GBN;

    const int sr = t >> 3;
    const int sk8 = (t & 7) * 8;

    float c[2][8][4];
    #pragma unroll
    for (int i = 0; i < 2; i++)
        #pragma unroll
        for (int j = 0; j < 8; j++)
            #pragma unroll
            for (int qq = 0; qq < 4; qq++) c[i][j][qq] = 0.f;

    auto stage = [&](int ch, int buf) {
        const int kc = ch & 3;
        const int acol = kc * 64 + ((ch >= 4 && ch < 8) ? 256 : 0);
        const __nv_bfloat16* Bb = (ch < 8) ? g_Bhi : g_Blo;
        const u32 abase = sbase + buf * TBYTES;
        const u32 bbase = sbase + 2 * TBYTES + buf * TBYTES;
        #pragma unroll
        for (int i = 0; i < 4; i++) {
            const int r = sr + i * 32;
            cpasync16(abase + r * (ASTR * 2) + sk8 * 2,
                      &g_A2[(size_t)(rowBase + r) * 512 + acol + sk8]);
            cpasync16(bbase + r * (ASTR * 2) + sk8 * 2,
                      &Bb[(size_t)(colBase + r) * 256 + kc * 64 + sk8]);
        }
        asm volatile("cp.async.commit_group;" ::: "memory");
    };

    stage(0, 0);

    for (int ch = 0; ch < 12; ch++) {
        const int buf = ch & 1;
        if (ch + 1 < 12) {
            stage(ch + 1, buf ^ 1);
            asm volatile("cp.async.wait_group 1;" ::: "memory");
        } else {
            asm volatile("cp.async.wait_group 0;" ::: "memory");
        }
        __syncthreads();

        const u32 abase = sbase + buf * TBYTES;
        const u32 bbase = sbase + 2 * TBYTES + buf * TBYTES;
        #pragma unroll
        for (int kk = 0; kk < 4; kk++) {
            const int k0 = kk * 16;
            u32 a[2][4], b[4][4];
            #pragma unroll
            for (int i = 0; i < 2; i++)
                ldsm4(a[i], abase + (warpM * 32 + i * 16 + aro) * (ASTR * 2)
                                  + (k0 + ako) * 2);
            #pragma unroll
            for (int jp = 0; jp < 4; jp++)
                ldsm4(b[jp], bbase + (warpN * 64 + jp * 16 + bro) * (ASTR * 2)
                                   + (k0 + bko) * 2);
            #pragma unroll
            for (int i = 0; i < 2; i++)
                #pragma unroll
                for (int jp = 0; jp < 4; jp++) {
                    mma_bf16(c[i][2 * jp],     a[i], &b[jp][0]);
                    mma_bf16(c[i][2 * jp + 1], a[i], &b[jp][2]);
                }
        }
        __syncthreads();
    }

    #pragma unroll
    for (int i = 0; i < 2; i++) {
        const int r0 = rowBase + warpM * 32 + i * 16 + lr;
        const int r1 = r0 + 8;
        float inv0 = 0.f, sg0 = 0.f, inv1 = 0.f, sg1 = 0.f;
        if (r0 < S) {
            const float d = g_denom[r0];
            inv0 = __fdividef(1.f, d + 1e-10f); sg0 = d * inv0;
        }
        if (r1 < S) {
            const float d = g_denom[r1];
            inv1 = __fdividef(1.f, d + 1e-10f); sg1 = d * inv1;
        }
        #pragma unroll
        for (int j = 0; j < 8; j++) {
            const int n = colBase + warpN * 64 + j * 8 + lc * 2;
            const float2 bm2 = *(const float2*)&bmv_[n];
            if (r0 < S) {
                float2 o;
                o.x = fmaf(c[i][j][0], inv0, sg0 * bm2.x);
                o.y = fmaf(c[i][j][1], inv0, sg0 * bm2.y);
                *(float2*)&out[(size_t)r0 * 256 + n] = o;
            }
            if (r1 < S) {
                float2 o;
                o.x = fmaf(c[i][j][2], inv1, sg1 * bm2.x);
                o.y = fmaf(c[i][j][3], inv1, sg1 * bm2.y);
                *(float2*)&out[(size_t)r1 * 256 + n] = o;
            }
        }
    }
}

// ===========================================================================
// inputs (metadata order): x, weights, Wg, bg, Wm, bm, p, index, [num_segments]
// ===========================================================================
extern "C" void kernel_launch(void* const* d_in, const int* in_sizes, int n_in,
                              void* d_out, int out_size) {
    const float* x       = (const float*)d_in[0];
    const float* weights = (const float*)d_in[1];
    const float* Wg      = (const float*)d_in[2];
    const float* bg      = (const float*)d_in[3];
    const float* Wm      = (const float*)d_in[4];
    const float* bm      = (const float*)d_in[5];
    const float* p       = (const float*)d_in[6];
    const int*   index   = (const int*)d_in[7];

    const int N = in_sizes[7];
    const int D = in_sizes[2];            // 256
    int S = out_size / D;                 // 20000
    if (S > S_MAX) S = S_MAX;

    cudaFuncSetAttribute(mma_gemm_kernel,
                         cudaFuncAttributeMaxDynamicSharedMemorySize, GEMM_SMEM);

    prep_b_kernel<<<256, 256>>>(Wm);
    zero_kernel<<<(S_MAX * (D_FIX / 4) + 255) / 256, 256>>>();
    node_pool_kernel<<<(N + CHUNK - 1) / CHUNK, 256, POOL_SMEM>>>(
        x, weights, Wg, bg, p, index, N);
    convert_a_kernel<<<(S_PAD * 64 + 255) / 256, 256>>>(S);
    dim3 grid((S + GBM - 1) / GBM, D / GBN);
    mma_gemm_kernel<<<grid, 256, GEMM_SMEM>>>(bm, (float*)d_out, S);
}